// round 8
// baseline (speedup 1.0000x reference)
#include <cuda_runtime.h>
#include <math.h>

#define Bn 64
#define Nn 128
#define Dn 32
#define Gn 127              // N-1
#define Pn (Nn*(Nn-1))      // 16256
#define HFn 16
#define EPSf 1e-5f

// ---------------- scratch (static device globals; no allocation) -------------
__device__ float g_U[Bn*Nn*Dn];      // U'[b][n][c] = x@W1_top + b1
__device__ float g_V[Bn*Nn*Dn];      // V [b][n][c] = x@W1_bot
__device__ float g_sumU[Nn], g_sumU2[Nn], g_sumV[Nn], g_sumV2[Nn];
__device__ float g_C[Nn*Nn];         // C[s][t] = sum_{b,c} U'[b,s,c]*V[b,t,c]
__device__ float g_f[Bn*Nn*HFn];     // pre-LN features of final MLP
__device__ float g_fsum[HFn], g_fsum2[HFn];

__device__ __forceinline__ float leaky(float x) { return x > 0.f ? x : 0.01f * x; }

// ---------------- Kernel A: per-node projections + stats + zeroing -----------
__global__ void kA(const float* __restrict__ inp, const float* __restrict__ W1,
                   const float* __restrict__ b1) {
    const int n = blockIdx.x;
    const int b = threadIdx.x;     // 0..63
    __shared__ __align__(16) float W1t[32*64];   // W1t[c*64 + k] = W1[k*32 + c]
    __shared__ float red[64*4];

    // zero g_C slice + f-stat accumulators (consumed by later kernels)
    g_C[n*128 + b*2]     = 0.f;
    g_C[n*128 + b*2 + 1] = 0.f;
    if (n == 0 && b < HFn) { g_fsum[b] = 0.f; g_fsum2[b] = 0.f; }

    for (int idx = b; idx < 2048; idx += 64) {
        int k = idx & 63, c = idx >> 6;
        W1t[c*64 + k] = W1[k*32 + c];
    }
    __syncthreads();

    float x[32];
    const float4* xp = (const float4*)(inp + ((size_t)b*Nn + n)*Dn);
    #pragma unroll
    for (int q = 0; q < 8; q++) {
        float4 v = xp[q];
        x[4*q+0]=v.x; x[4*q+1]=v.y; x[4*q+2]=v.z; x[4*q+3]=v.w;
    }
    float su=0.f, su2=0.f, sv=0.f, sv2=0.f;
    float* Uo = g_U + ((size_t)b*Nn + n)*Dn;
    float* Vo = g_V + ((size_t)b*Nn + n)*Dn;
    #pragma unroll 4
    for (int c = 0; c < 32; c++) {
        const float4* wr = (const float4*)(W1t + c*64);
        float u = b1[c];
        float v = 0.f;
        #pragma unroll
        for (int j = 0; j < 8; j++) {
            float4 wu = wr[j];
            float4 wv = wr[8 + j];
            u += x[4*j+0]*wu.x + x[4*j+1]*wu.y + x[4*j+2]*wu.z + x[4*j+3]*wu.w;
            v += x[4*j+0]*wv.x + x[4*j+1]*wv.y + x[4*j+2]*wv.z + x[4*j+3]*wv.w;
        }
        Uo[c] = u; Vo[c] = v;
        su += u; su2 += u*u; sv += v; sv2 += v*v;
    }
    red[b] = su; red[64+b] = su2; red[128+b] = sv; red[192+b] = sv2;
    __syncthreads();
    for (int s = 32; s > 0; s >>= 1) {
        if (b < s) {
            red[b]     += red[b+s];
            red[64+b]  += red[64+b+s];
            red[128+b] += red[128+b+s];
            red[192+b] += red[192+b+s];
        }
        __syncthreads();
    }
    if (b == 0) {
        g_sumU[n]  = red[0];
        g_sumU2[n] = red[64];
        g_sumV[n]  = red[128];
        g_sumV2[n] = red[192];
    }
}

// ---------------- Kernel B: cross term C[s,t], K-split x8 --------------------
__global__ void kB() {
    const int t0 = blockIdx.x * 16;
    const int s0 = blockIdx.y * 16;
    const int bz = blockIdx.z * 8;
    const int tx = threadIdx.x & 15;
    const int ty = threadIdx.x >> 4;
    __shared__ __align__(16) float Us[16][36];
    __shared__ __align__(16) float Vs[16][36];
    float acc = 0.f;
    for (int b = bz; b < bz + 8; b++) {
        __syncthreads();
        {
            int idx = threadIdx.x;
            int r = idx >> 5, c = idx & 31;
            Us[r][c] = g_U[((size_t)b*Nn + s0 + r)*Dn + c];
            Vs[r][c] = g_V[((size_t)b*Nn + t0 + r)*Dn + c];
            idx += 256; r = idx >> 5; c = idx & 31;
            Us[r][c] = g_U[((size_t)b*Nn + s0 + r)*Dn + c];
            Vs[r][c] = g_V[((size_t)b*Nn + t0 + r)*Dn + c];
        }
        __syncthreads();
        #pragma unroll
        for (int q = 0; q < 8; q++) {
            float4 u = *(const float4*)&Us[ty][4*q];
            float4 v = *(const float4*)&Vs[tx][4*q];
            acc += u.x*v.x + u.y*v.y + u.z*v.z + u.w*v.w;
        }
    }
    atomicAdd(&g_C[(s0+ty)*Nn + (t0+tx)], acc);
}

// ---------------- Kernel C: fused per-edge MLP, 2x2-batch groups -------------
// grid = (N, B/4), block = 128, dynamic smem, 3 CTAs/SM.
struct SC {
    float W2s[1024];        // W2[k][c] original layout
    float W3s[1056];        // W3[c][33] original layout
    float w3c0[32];         // W3[c][0]
    float b2s[32];
    float b3s[36];
    float us[4][32];
    float xs[4][32];
    float gw[4][4];         // [warp][batch 0..3] gate partial sums
    float zs[4*32];         // z[b][c]
    float aggs[4*32];       // agg[b][d]
    float4 Vt[2][8][128];   // staged V for current 2-batch group   (32 KB)
    float  red[2][32*Gn];   // gate*a2, k-major, current group      (31.8 KB)
};

__global__ void __launch_bounds__(128, 3) kC(
        const float* __restrict__ inp,
        const float* __restrict__ W2, const float* __restrict__ b2,
        const float* __restrict__ W3, const float* __restrict__ b3,
        const float* __restrict__ Wf1, const float* __restrict__ bf1,
        const float* __restrict__ g1, const float* __restrict__ be1,
        float* __restrict__ outEdges) {
    extern __shared__ __align__(16) char smem_raw[];
    SC* S = (SC*)smem_raw;

    const int i  = blockIdx.x;
    const int bb = blockIdx.y * 4;
    const int e  = threadIdx.x;      // 0..127
    const int warp = e >> 5;
    const int lane = e & 31;

    // ---- init loads ----
    for (int idx = e; idx < 1024; idx += 128) S->W2s[idx] = W2[idx];
    for (int idx = e; idx < 1056; idx += 128) S->W3s[idx] = W3[idx];
    if (e < 32) { S->w3c0[e] = W3[e*33]; S->b2s[e] = b2[e]; }
    if (e < 33) S->b3s[e] = b3[e];
    {
        const int b = e >> 5, k = e & 31;
        S->us[b][k] = g_U[((size_t)(bb+b)*Nn + i)*Dn + k];
        S->xs[b][k] = inp[((size_t)(bb+b)*Nn + i)*Dn + k];
    }

    // LN scale/shift (depends on p only; hoisted, same for all batches)
    float sc = 0.f, sh = 0.f;
    int t = 0, p = 0;
    if (e < Gn) {
        t = e + (e >= i);
        p = i * Gn + e;
        const float inv = 1.0f / 2048.0f;
        float m  = (g_sumU[i] + g_sumV[t]) * inv;
        float e2 = (g_sumU2[i] + g_sumV2[t] + 2.0f * g_C[i*Nn + t]) * inv;
        sc = rsqrtf(e2 - m*m + EPSf) * g1[p];
        sh = be1[p] - m * sc;
    }

    #pragma unroll
    for (int g = 0; g < 2; g++) {
        // ---- stage V for batches bb+2g, bb+2g+1 (coalesced) ----
        {
            const float4* gsrc = (const float4*)(g_V + (size_t)(bb + 2*g)*Nn*Dn);
            #pragma unroll
            for (int m = 0; m < 16; m++) {
                int f = m*128 + e;              // 0..2047 float4s
                int b = f >> 10, rem = f & 1023, tt = rem >> 3, q = rem & 7;
                S->Vt[b][q][tt] = gsrc[f];
            }
        }
        __syncthreads();

        float gate0 = 0.f, gate1 = 0.f;
        if (e < Gn) {
            float acc0[32], acc1[32];
            #pragma unroll
            for (int c = 0; c < 32; c++) { acc0[c] = 0.f; acc1[c] = 0.f; }

            const float* u0 = S->us[2*g + 0];
            const float* u1 = S->us[2*g + 1];

            #pragma unroll
            for (int q = 0; q < 8; q++) {
                float4 v0 = S->Vt[0][q][t];
                float4 v1 = S->Vt[1][q][t];
                float a0[4], a1[4];
                a0[0] = leaky((u0[4*q+0]+v0.x)*sc+sh);
                a0[1] = leaky((u0[4*q+1]+v0.y)*sc+sh);
                a0[2] = leaky((u0[4*q+2]+v0.z)*sc+sh);
                a0[3] = leaky((u0[4*q+3]+v0.w)*sc+sh);
                a1[0] = leaky((u1[4*q+0]+v1.x)*sc+sh);
                a1[1] = leaky((u1[4*q+1]+v1.y)*sc+sh);
                a1[2] = leaky((u1[4*q+2]+v1.z)*sc+sh);
                a1[3] = leaky((u1[4*q+3]+v1.w)*sc+sh);

                #pragma unroll
                for (int j = 0; j < 4; j++) {
                    const int k = 4*q + j;
                    const float4* wrow = (const float4*)(S->W2s + k*32);
                    #pragma unroll
                    for (int c4 = 0; c4 < 8; c4++) {
                        float4 w = wrow[c4];
                        acc0[c4*4+0] += a0[j]*w.x;  acc0[c4*4+1] += a0[j]*w.y;
                        acc0[c4*4+2] += a0[j]*w.z;  acc0[c4*4+3] += a0[j]*w.w;
                        acc1[c4*4+0] += a1[j]*w.x;  acc1[c4*4+1] += a1[j]*w.y;
                        acc1[c4*4+2] += a1[j]*w.z;  acc1[c4*4+3] += a1[j]*w.w;
                    }
                }
            }

            // bias + leaky + gate dot
            float ga0 = S->b3s[0], ga1 = S->b3s[0];
            #pragma unroll
            for (int c = 0; c < 32; c++) {
                float bc = S->b2s[c];
                acc0[c] = leaky(acc0[c] + bc);
                acc1[c] = leaky(acc1[c] + bc);
                float w0 = S->w3c0[c];
                ga0 += acc0[c]*w0; ga1 += acc1[c]*w0;
            }
            gate0 = 1.0f / (1.0f + __expf(-ga0));
            gate1 = 1.0f / (1.0f + __expf(-ga1));
            outEdges[(size_t)(bb + 2*g + 0)*Pn + p] = gate0;
            outEdges[(size_t)(bb + 2*g + 1)*Pn + p] = gate1;

            // weighted activations into red (k-major, conflict-free)
            #pragma unroll
            for (int c = 0; c < 32; c++) {
                S->red[0][c*Gn + e] = gate0 * acc0[c];
                S->red[1][c*Gn + e] = gate1 * acc1[c];
            }
        }

        // warp-reduce gate sums
        {
            float v0 = gate0, v1 = gate1;
            #pragma unroll
            for (int s = 16; s > 0; s >>= 1) {
                v0 += __shfl_xor_sync(0xffffffffu, v0, s);
                v1 += __shfl_xor_sync(0xffffffffu, v1, s);
            }
            if (lane == 0) {
                S->gw[warp][2*g + 0] = v0;
                S->gw[warp][2*g + 1] = v1;
            }
        }
        __syncthreads();

        // z reduction: threads 0..63 -> (b in group, c)
        if (e < 64) {
            const int b = e >> 5, c = e & 31;
            const float* rr = &S->red[b][c*Gn];
            float s0 = 0.f, s1 = 0.f, s2 = 0.f, s3 = 0.f;
            int r = 0;
            #pragma unroll 4
            for (; r + 4 <= Gn; r += 4) {
                s0 += rr[r]; s1 += rr[r+1]; s2 += rr[r+2]; s3 += rr[r+3];
            }
            for (; r < Gn; r++) s0 += rr[r];
            S->zs[(2*g + b)*32 + c] = (s0 + s1) + (s2 + s3);
        }
        // next-iteration staging __syncthreads orders red/Vt reuse;
        // (for g=1 the sync below orders zs for the agg phase)
        __syncthreads();
    }

    // agg[b][d] = G[b]*b3[d+1] + sum_c z[b][c] * W3[c][d+1]
    {
        const int b = e >> 5, d = e & 31;
        float G = S->gw[0][b] + S->gw[1][b] + S->gw[2][b] + S->gw[3][b];
        float acc = G * S->b3s[d+1];
        const float* zb = &S->zs[b*32];
        #pragma unroll
        for (int c = 0; c < 32; c++) acc += zb[c] * S->W3s[c*33 + (d+1)];
        S->aggs[b*32 + d] = acc;
    }
    __syncthreads();

    // f = [x, agg] @ Wf1 + bf1 ; accumulate column stats for the final LN
    if (e < 64) {
        const int b = e >> 4, c = e & 15;
        float acc = bf1[c];
        #pragma unroll
        for (int k = 0; k < 32; k++) acc += S->xs[b][k] * Wf1[k*HFn + c];
        #pragma unroll
        for (int k = 0; k < 32; k++) acc += S->aggs[b*32 + k] * Wf1[(32+k)*HFn + c];
        g_f[((size_t)(bb+b)*Nn + i)*HFn + c] = acc;
        atomicAdd(&g_fsum[c],  acc);
        atomicAdd(&g_fsum2[c], acc*acc);
    }
}

// ---------------- Kernel F: final LN (inline params) + MLP -> out -------------
// grid = 128, block = 64: one row per thread, all SMs engaged
__global__ void kF(const float* __restrict__ gf, const float* __restrict__ bef,
                   const float* __restrict__ Wf2, const float* __restrict__ bf2,
                   float* __restrict__ outp) {
    __shared__ __align__(16) float Wf2s[16*32];
    __shared__ float lnsc[16], lnsh[16], bf2s[32];
    const int tid = threadIdx.x;
    for (int idx = tid; idx < 16*32; idx += 64) Wf2s[idx] = Wf2[idx];
    if (tid < 16) {
        const float invR = 1.0f / 8192.0f;
        float mean = g_fsum[tid] * invR;
        float var  = g_fsum2[tid] * invR - mean * mean;
        float sc = rsqrtf(var + EPSf) * gf[tid];
        lnsc[tid] = sc;
        lnsh[tid] = bef[tid] - mean * sc;
    }
    if (tid < 32) bf2s[tid] = bf2[tid];
    __syncthreads();

    const int r = blockIdx.x * 64 + tid;   // 0..8191
    float gq[16];
    #pragma unroll
    for (int j = 0; j < 16; j++) {
        float v = g_f[(size_t)r*HFn + j];
        gq[j] = leaky(v * lnsc[j] + lnsh[j]);
    }
    float4* op = (float4*)(outp + (size_t)r * Dn);
    #pragma unroll
    for (int q = 0; q < 8; q++) {
        float o[4];
        #pragma unroll
        for (int u = 0; u < 4; u++) {
            int c = 4*q + u;
            float acc = bf2s[c];
            #pragma unroll
            for (int j = 0; j < 16; j++) acc += gq[j] * Wf2s[j*32 + c];
            o[u] = acc;
        }
        op[q] = make_float4(o[0], o[1], o[2], o[3]);
    }
}

// ---------------- launch ------------------------------------------------------
extern "C" void kernel_launch(void* const* d_in, const int* in_sizes, int n_in,
                              void* d_out, int out_size) {
    const float* inp = (const float*)d_in[0];
    const float* W1  = (const float*)d_in[3];
    const float* b1  = (const float*)d_in[4];
    const float* g1  = (const float*)d_in[5];
    const float* be1 = (const float*)d_in[6];
    const float* W2  = (const float*)d_in[7];
    const float* b2  = (const float*)d_in[8];
    const float* W3  = (const float*)d_in[9];
    const float* b3  = (const float*)d_in[10];
    const float* Wf1 = (const float*)d_in[11];
    const float* bf1 = (const float*)d_in[12];
    const float* gf  = (const float*)d_in[13];
    const float* bef = (const float*)d_in[14];
    const float* Wf2 = (const float*)d_in[15];
    const float* bf2 = (const float*)d_in[16];

    float* outEdges = (float*)d_out;                       // (B, P)
    float* outFeat  = (float*)d_out + (size_t)Bn * Pn;     // (B, N, D)

    const int smemC = (int)sizeof(SC);
    cudaFuncSetAttribute(kC, cudaFuncAttributeMaxDynamicSharedMemorySize, smemC);

    kA<<<Nn, 64>>>(inp, W1, b1);
    kB<<<dim3(8, 8, 8), 256>>>();
    kC<<<dim3(Nn, Bn/4), 128, smemC>>>(inp, W2, b2, W3, b3, Wf1, bf1, g1, be1, outEdges);
    kF<<<128, 64>>>(gf, bef, Wf2, bf2, outFeat);
}

// round 9
// speedup vs baseline: 1.0176x; 1.0176x over previous
#include <cuda_runtime.h>
#include <math.h>

#define Bn 64
#define Nn 128
#define Dn 32
#define Gn 127              // N-1
#define Pn (Nn*(Nn-1))      // 16256
#define HFn 16
#define EPSf 1e-5f

// ---------------- scratch (static device globals; no allocation) -------------
__device__ float g_U[Bn*Nn*Dn];      // U'[b][n][c] = x@W1_top + b1
__device__ float g_V[Bn*Nn*Dn];      // V [b][n][c] = x@W1_bot
__device__ float g_sumU[Nn], g_sumU2[Nn], g_sumV[Nn], g_sumV2[Nn];
__device__ float g_C[Nn*Nn];         // C[s][t] = sum_{b,c} U'[b,s,c]*V[b,t,c]
__device__ float g_f[Bn*Nn*HFn];     // pre-LN features of final MLP
__device__ float g_fsum[HFn], g_fsum2[HFn];

__device__ __forceinline__ float leaky(float x) { return x > 0.f ? x : 0.01f * x; }

// ---------------- Kernel A: per-node projections + stats + zeroing -----------
__global__ void kA(const float* __restrict__ inp, const float* __restrict__ W1,
                   const float* __restrict__ b1) {
    const int n = blockIdx.x;
    const int b = threadIdx.x;     // 0..63
    __shared__ __align__(16) float W1t[32*64];   // W1t[c*64 + k] = W1[k*32 + c]
    __shared__ float red[64*4];

    // zero g_C slice + f-stat accumulators (consumed by later kernels)
    g_C[n*128 + b*2]     = 0.f;
    g_C[n*128 + b*2 + 1] = 0.f;
    if (n == 0 && b < HFn) { g_fsum[b] = 0.f; g_fsum2[b] = 0.f; }

    for (int idx = b; idx < 2048; idx += 64) {
        int k = idx & 63, c = idx >> 6;
        W1t[c*64 + k] = W1[k*32 + c];
    }
    __syncthreads();

    float x[32];
    const float4* xp = (const float4*)(inp + ((size_t)b*Nn + n)*Dn);
    #pragma unroll
    for (int q = 0; q < 8; q++) {
        float4 v = xp[q];
        x[4*q+0]=v.x; x[4*q+1]=v.y; x[4*q+2]=v.z; x[4*q+3]=v.w;
    }
    float su=0.f, su2=0.f, sv=0.f, sv2=0.f;
    float* Uo = g_U + ((size_t)b*Nn + n)*Dn;
    float* Vo = g_V + ((size_t)b*Nn + n)*Dn;
    #pragma unroll 4
    for (int c = 0; c < 32; c++) {
        const float4* wr = (const float4*)(W1t + c*64);
        float u = b1[c];
        float v = 0.f;
        #pragma unroll
        for (int j = 0; j < 8; j++) {
            float4 wu = wr[j];
            float4 wv = wr[8 + j];
            u += x[4*j+0]*wu.x + x[4*j+1]*wu.y + x[4*j+2]*wu.z + x[4*j+3]*wu.w;
            v += x[4*j+0]*wv.x + x[4*j+1]*wv.y + x[4*j+2]*wv.z + x[4*j+3]*wv.w;
        }
        Uo[c] = u; Vo[c] = v;
        su += u; su2 += u*u; sv += v; sv2 += v*v;
    }
    red[b] = su; red[64+b] = su2; red[128+b] = sv; red[192+b] = sv2;
    __syncthreads();
    for (int s = 32; s > 0; s >>= 1) {
        if (b < s) {
            red[b]     += red[b+s];
            red[64+b]  += red[64+b+s];
            red[128+b] += red[128+b+s];
            red[192+b] += red[192+b+s];
        }
        __syncthreads();
    }
    if (b == 0) {
        g_sumU[n]  = red[0];
        g_sumU2[n] = red[64];
        g_sumV[n]  = red[128];
        g_sumV2[n] = red[192];
    }
}

// ---------------- Kernel B: cross term C[s,t], K-split x8 --------------------
__global__ void kB() {
    const int t0 = blockIdx.x * 16;
    const int s0 = blockIdx.y * 16;
    const int bz = blockIdx.z * 8;
    const int tx = threadIdx.x & 15;
    const int ty = threadIdx.x >> 4;
    __shared__ __align__(16) float Us[16][36];
    __shared__ __align__(16) float Vs[16][36];
    float acc = 0.f;
    for (int b = bz; b < bz + 8; b++) {
        __syncthreads();
        {
            int idx = threadIdx.x;
            int r = idx >> 5, c = idx & 31;
            Us[r][c] = g_U[((size_t)b*Nn + s0 + r)*Dn + c];
            Vs[r][c] = g_V[((size_t)b*Nn + t0 + r)*Dn + c];
            idx += 256; r = idx >> 5; c = idx & 31;
            Us[r][c] = g_U[((size_t)b*Nn + s0 + r)*Dn + c];
            Vs[r][c] = g_V[((size_t)b*Nn + t0 + r)*Dn + c];
        }
        __syncthreads();
        #pragma unroll
        for (int q = 0; q < 8; q++) {
            float4 u = *(const float4*)&Us[ty][4*q];
            float4 v = *(const float4*)&Vs[tx][4*q];
            acc += u.x*v.x + u.y*v.y + u.z*v.z + u.w*v.w;
        }
    }
    atomicAdd(&g_C[(s0+ty)*Nn + (t0+tx)], acc);
}

// ---------------- Kernel C: fused per-edge MLP, 1 batch-edge per thread ------
// grid = (N, B/2), block = 256, dynamic smem, 4 CTAs/SM target.
struct SC {
    float W2s[1024];        // W2[k][c] original layout
    float W3s[1056];        // W3[c][33] original layout
    float w3c0[32];         // W3[c][0]
    float b2s[32];
    float b3s[36];
    float us[2][32];
    float xs[2][32];
    float zs[2][33];        // z[b][c]; c=32 holds gate sum G
    float aggs[2][32];      // agg[b][d]
    union {
        float4 Vt[2][8][128];    // staged V (32 KB)
        float  red[2][33*Gn];    // gate*a2 + gate channel (33.5 KB)
    } u;
};

__global__ void __launch_bounds__(256, 4) kC(
        const float* __restrict__ inp,
        const float* __restrict__ W2, const float* __restrict__ b2,
        const float* __restrict__ W3, const float* __restrict__ b3,
        const float* __restrict__ Wf1, const float* __restrict__ bf1,
        const float* __restrict__ g1, const float* __restrict__ be1,
        float* __restrict__ outEdges) {
    extern __shared__ __align__(16) char smem_raw[];
    SC* S = (SC*)smem_raw;

    const int i  = blockIdx.x;
    const int bb = blockIdx.y * 2;
    const int e  = threadIdx.x;      // 0..255

    // ---- init loads ----
    for (int idx = e; idx < 1024; idx += 256) S->W2s[idx] = W2[idx];
    for (int idx = e; idx < 1056; idx += 256) S->W3s[idx] = W3[idx];
    if (e < 32) { S->w3c0[e] = W3[e*33]; S->b2s[e] = b2[e]; }
    if (e < 33) S->b3s[e] = b3[e];
    if (e < 64) {
        const int b = e >> 5, k = e & 31;
        S->us[b][k] = g_U[((size_t)(bb+b)*Nn + i)*Dn + k];
        S->xs[b][k] = inp[((size_t)(bb+b)*Nn + i)*Dn + k];
    }
    // ---- stage V tile (2 batches x 128 rows x 32 floats), coalesced ----
    {
        const float4* gsrc = (const float4*)(g_V + (size_t)bb*Nn*Dn);
        #pragma unroll
        for (int m = 0; m < 8; m++) {
            int f = m*256 + e;                 // 0..2047 float4s
            int b = f >> 10, rem = f & 1023, tt = rem >> 3, q = rem & 7;
            S->u.Vt[b][q][tt] = gsrc[f];
        }
    }
    __syncthreads();

    const bool active = (e < 2*Gn);            // 254 workers
    const int  b    = active ? (e / Gn) : 0;   // batch within pair
    const int  edge = active ? (e % Gn) : 0;

    float gate = 0.f;
    float acc[32];

    if (active) {
        const int t = edge + (edge >= i);
        const int p = i * Gn + edge;

        // LN scale/shift (depends on p only)
        const float inv = 1.0f / 2048.0f;
        float m  = (g_sumU[i] + g_sumV[t]) * inv;
        float e2 = (g_sumU2[i] + g_sumV2[t] + 2.0f * g_C[i*Nn + t]) * inv;
        float sc = rsqrtf(e2 - m*m + EPSf) * g1[p];
        float sh = be1[p] - m * sc;

        #pragma unroll
        for (int c = 0; c < 32; c++) acc[c] = 0.f;

        const float* ub = S->us[b];
        #pragma unroll
        for (int q = 0; q < 8; q++) {
            float4 v = S->u.Vt[b][q][t];
            float a0 = leaky((ub[4*q+0] + v.x) * sc + sh);
            float a1 = leaky((ub[4*q+1] + v.y) * sc + sh);
            float a2 = leaky((ub[4*q+2] + v.z) * sc + sh);
            float a3 = leaky((ub[4*q+3] + v.w) * sc + sh);

            #pragma unroll
            for (int j = 0; j < 4; j++) {
                const float aj = (j==0) ? a0 : (j==1) ? a1 : (j==2) ? a2 : a3;
                const float4* wrow = (const float4*)(S->W2s + (4*q+j)*32);
                #pragma unroll
                for (int c4 = 0; c4 < 8; c4++) {
                    float4 w = wrow[c4];
                    acc[c4*4+0] += aj*w.x;  acc[c4*4+1] += aj*w.y;
                    acc[c4*4+2] += aj*w.z;  acc[c4*4+3] += aj*w.w;
                }
            }
        }

        // bias + leaky + gate dot (layer-3 column 0)
        float ga = S->b3s[0];
        #pragma unroll
        for (int c = 0; c < 32; c++) {
            acc[c] = leaky(acc[c] + S->b2s[c]);
            ga += acc[c] * S->w3c0[c];
        }
        gate = 1.0f / (1.0f + __expf(-ga));
        outEdges[(size_t)(bb+b)*Pn + p] = gate;
    }

    __syncthreads();   // all Vt reads done -> safe to overwrite union with red

    if (active) {
        #pragma unroll
        for (int c = 0; c < 32; c++)
            S->u.red[b][c*Gn + edge] = gate * acc[c];
        S->u.red[b][32*Gn + edge] = gate;      // gate as channel 32
    }
    __syncthreads();

    // z reduction: 66 threads, each sums 127 values of one (b, c) channel
    if (e < 66) {
        const int zb = (e >= 33);
        const int c  = e - zb*33;
        const float* rr = &S->u.red[zb][c*Gn];
        float s0 = 0.f, s1 = 0.f, s2 = 0.f, s3 = 0.f;
        int r = 0;
        #pragma unroll 4
        for (; r + 4 <= Gn; r += 4) {
            s0 += rr[r]; s1 += rr[r+1]; s2 += rr[r+2]; s3 += rr[r+3];
        }
        for (; r < Gn; r++) s0 += rr[r];
        S->zs[zb][c] = (s0 + s1) + (s2 + s3);
    }
    __syncthreads();

    // agg[b][d] = G[b]*b3[d+1] + sum_c z[b][c] * W3[c][d+1]
    if (e < 64) {
        const int ab = e >> 5, d = e & 31;
        const float G = S->zs[ab][32];
        float a = G * S->b3s[d+1];
        const float* zb = S->zs[ab];
        #pragma unroll
        for (int c = 0; c < 32; c++) a += zb[c] * S->W3s[c*33 + (d+1)];
        S->aggs[ab][d] = a;
    }
    __syncthreads();

    // f = [x, agg] @ Wf1 + bf1 ; accumulate column stats for the final LN
    if (e < 32) {
        const int fb = e >> 4, c = e & 15;
        float a = bf1[c];
        #pragma unroll
        for (int k = 0; k < 32; k++) a += S->xs[fb][k] * Wf1[k*HFn + c];
        #pragma unroll
        for (int k = 0; k < 32; k++) a += S->aggs[fb][k] * Wf1[(32+k)*HFn + c];
        g_f[((size_t)(bb+fb)*Nn + i)*HFn + c] = a;
        atomicAdd(&g_fsum[c],  a);
        atomicAdd(&g_fsum2[c], a*a);
    }
}

// ---------------- Kernel F: final LN (inline params) + MLP -> out -------------
// grid = 128, block = 128: two threads per row (16 output channels each)
__global__ void kF(const float* __restrict__ gf, const float* __restrict__ bef,
                   const float* __restrict__ Wf2, const float* __restrict__ bf2,
                   float* __restrict__ outp) {
    __shared__ __align__(16) float Wf2s[16*32];
    __shared__ float lnsc[16], lnsh[16], bf2s[32];
    const int tid = threadIdx.x;
    for (int idx = tid; idx < 16*32; idx += 128) Wf2s[idx] = Wf2[idx];
    if (tid < 16) {
        const float invR = 1.0f / 8192.0f;
        float mean = g_fsum[tid] * invR;
        float var  = g_fsum2[tid] * invR - mean * mean;
        float sc = rsqrtf(var + EPSf) * gf[tid];
        lnsc[tid] = sc;
        lnsh[tid] = bef[tid] - mean * sc;
    }
    if (tid < 32) bf2s[tid] = bf2[tid];
    __syncthreads();

    const int gt = blockIdx.x * 128 + tid;   // 0..16383
    const int r = gt >> 1;                   // row 0..8191
    const int half = (gt & 1) * 16;          // output channel base

    float gq[16];
    #pragma unroll
    for (int j = 0; j < 16; j++) {
        float v = g_f[(size_t)r*HFn + j];
        gq[j] = leaky(v * lnsc[j] + lnsh[j]);
    }
    float4* op = (float4*)(outp + (size_t)r * Dn + half);
    #pragma unroll
    for (int q = 0; q < 4; q++) {
        float o[4];
        #pragma unroll
        for (int u = 0; u < 4; u++) {
            int c = half + 4*q + u;
            float a = bf2s[c];
            #pragma unroll
            for (int j = 0; j < 16; j++) a += gq[j] * Wf2s[j*32 + c];
            o[u] = a;
        }
        op[q] = make_float4(o[0], o[1], o[2], o[3]);
    }
}

// ---------------- launch ------------------------------------------------------
extern "C" void kernel_launch(void* const* d_in, const int* in_sizes, int n_in,
                              void* d_out, int out_size) {
    const float* inp = (const float*)d_in[0];
    const float* W1  = (const float*)d_in[3];
    const float* b1  = (const float*)d_in[4];
    const float* g1  = (const float*)d_in[5];
    const float* be1 = (const float*)d_in[6];
    const float* W2  = (const float*)d_in[7];
    const float* b2  = (const float*)d_in[8];
    const float* W3  = (const float*)d_in[9];
    const float* b3  = (const float*)d_in[10];
    const float* Wf1 = (const float*)d_in[11];
    const float* bf1 = (const float*)d_in[12];
    const float* gf  = (const float*)d_in[13];
    const float* bef = (const float*)d_in[14];
    const float* Wf2 = (const float*)d_in[15];
    const float* bf2 = (const float*)d_in[16];

    float* outEdges = (float*)d_out;                       // (B, P)
    float* outFeat  = (float*)d_out + (size_t)Bn * Pn;     // (B, N, D)

    const int smemC = (int)sizeof(SC);
    cudaFuncSetAttribute(kC, cudaFuncAttributeMaxDynamicSharedMemorySize, smemC);

    kA<<<Nn, 64>>>(inp, W1, b1);
    kB<<<dim3(8, 8, 8), 256>>>();
    kC<<<dim3(Nn, Bn/2), 256, smemC>>>(inp, W2, b2, W3, b3, Wf1, bf1, g1, be1, outEdges);
    kF<<<128, 128>>>(gf, bef, Wf2, bf2, outFeat);
}